// round 4
// baseline (speedup 1.0000x reference)
#include <cuda_runtime.h>
#include <cuda_fp16.h>

#define N_NODES 50000
#define F1 64
#define F2 128
#define F3 64
#define MAX_E 800000

// ---------------- device scratch ----------------
__device__ int     g_cnt [N_NODES];          // in-degree (excl. self-loop)
__device__ int2    g_ed  [MAX_E];            // packed {src, dst}
__device__ __half  g_zsh [N_NODES * F1];     // (z * dinv) as fp16, 128B/node
__device__ float   g_agg1[N_NODES * F1];     // seeded with z*dinv (fp32), += zs[s]
__device__ float   g_x   [N_NODES * F2];     // relu(layer1)
__device__ float   g_h2  [N_NODES * F3];     // x @ W2 (fp32)
__device__ __half  g_h2h [N_NODES * F3];     // (h2 * dinv) as fp16
__device__ int     g_is64;

__device__ __forceinline__ void red4(float* p, float x, float y, float z, float w) {
    asm volatile("red.global.add.v4.f32 [%0], {%1,%2,%3,%4};"
                 :: "l"(p), "f"(x), "f"(y), "f"(z), "f"(w) : "memory");
}

__device__ __forceinline__ float rinv_of(int m) {
    return rsqrtf((float)(g_cnt[m] + 1));
}

// ---------------- init: zero histogram + dtype detect ----------------
__global__ void init_kernel(const long long* ei, int M) {
    int i = blockIdx.x * 256 + threadIdx.x;
    if (i < M) g_cnt[i] = 0;
    if (blockIdx.x == 0 && threadIdx.x == 0) {
        bool ok = true;
#pragma unroll
        for (int k = 0; k < 8; k++) {
            long long v = ei[k];
            if (v < 0 || v >= N_NODES) ok = false;
        }
        g_is64 = ok ? 1 : 0;   // int32 data read as int64 lands out of range
    }
}

// ---------------- pack edges to int2 + degree histogram ----------------
__global__ void pack_deg_kernel(const void* ei, int nE) {
    int e = blockIdx.x * 256 + threadIdx.x;
    if (e >= nE) return;
    int s, d;
    if (g_is64) {
        s = (int)((const long long*)ei)[e];
        d = (int)((const long long*)ei)[(long long)nE + e];
    } else {
        s = ((const int*)ei)[e];
        d = ((const int*)ei)[nE + e];
    }
    g_ed[e] = make_int2(s, d);
    atomicAdd(&g_cnt[d], 1);
}

// ---------------- scale1: zsh = half(z*dinv), seed agg1 = z*dinv (fp32) ----------------
__global__ __launch_bounds__(256) void scale1_kernel(const float4* __restrict__ z4, int M) {
    int i = blockIdx.x * 256 + threadIdx.x;     // over M*16 float4
    if (i >= M * 16) return;
    float r = rinv_of(i >> 4);
    float4 v = z4[i];
    v.x *= r; v.y *= r; v.z *= r; v.w *= r;
    ((float4*)g_agg1)[i] = v;                   // self-loop seed (fp32)
    __half2* hp = (__half2*)g_zsh;
    hp[i * 2 + 0] = __floats2half2_rn(v.x, v.y);
    hp[i * 2 + 1] = __floats2half2_rn(v.z, v.w);
}

// ---------------- agg: 8 threads/edge, 16B fp16 gather, 2x red.v4 fp32 ----------------
__device__ __forceinline__ void agg_body(const __half* __restrict__ src,
                                         float* __restrict__ dst, int nE) {
    long long t = (long long)blockIdx.x * 256 + threadIdx.x;
    long long e = t >> 3;
    if (e >= nE) return;
    int j = (int)(t & 7);
    int2 ed = g_ed[e];
    float4 raw = ((const float4*)src)[(long long)ed.x * 8 + j];   // 8 halves
    const __half2* h = (const __half2*)&raw;
    float2 f0 = __half22float2(h[0]);
    float2 f1 = __half22float2(h[1]);
    float2 f2 = __half22float2(h[2]);
    float2 f3 = __half22float2(h[3]);
    float* p = dst + (long long)ed.y * 64 + j * 8;
    red4(p,     f0.x, f0.y, f1.x, f1.y);
    red4(p + 4, f2.x, f2.y, f3.x, f3.y);
}

__global__ __launch_bounds__(256) void agg1_kernel(int nE) {
    agg_body(g_zsh, g_agg1, nE);
}

__global__ __launch_bounds__(256) void agg2_kernel(float* __restrict__ out, int nE) {
    agg_body(g_h2h, out, nE);
}

// ---------------- GEMM1: x = relu( (agg1*dinv) @ W1 + b1 )  [M,64]x[64,128] ----------------
__global__ __launch_bounds__(256) void gemm1_kernel(const float* __restrict__ W1,
                                                    const float* __restrict__ b1,
                                                    int M) {
    __shared__ float  Ws[F1 * F2];        // 32 KB
    __shared__ float4 As4[64 * 16];       // 16 KB
    int tid = threadIdx.x;
    int m0  = blockIdx.x * 64;

    const float4* W14 = (const float4*)W1;
    float4* Ws4 = (float4*)Ws;
#pragma unroll
    for (int i = 0; i < 8; i++) Ws4[tid + 256 * i] = W14[tid + 256 * i];

    const float4* ag4 = (const float4*)g_agg1;
#pragma unroll
    for (int i = 0; i < 4; i++) {
        int t   = tid + 256 * i;
        int row = m0 + (t >> 4);
        float4 a = make_float4(0.f, 0.f, 0.f, 0.f);
        if (row < M) {
            a = ag4[(long long)row * 16 + (t & 15)];
            float r = rinv_of(row);
            a.x *= r; a.y *= r; a.z *= r; a.w *= r;
        }
        As4[t] = a;
    }
    __syncthreads();

    int tx = tid & 31, ty = tid >> 5;
    int c = tx * 4, r0 = ty * 8;
    float acc[8][4];
#pragma unroll
    for (int i = 0; i < 8; i++)
#pragma unroll
        for (int jj = 0; jj < 4; jj++) acc[i][jj] = 0.f;

    const float* As = (const float*)As4;
#pragma unroll
    for (int k = 0; k < F1; k++) {
        float4 wv = *(const float4*)&Ws[k * F2 + c];
#pragma unroll
        for (int i = 0; i < 8; i++) {
            float a = As[(r0 + i) * F1 + k];
            acc[i][0] += a * wv.x;
            acc[i][1] += a * wv.y;
            acc[i][2] += a * wv.z;
            acc[i][3] += a * wv.w;
        }
    }

    float4 bb = *(const float4*)&b1[c];
#pragma unroll
    for (int i = 0; i < 8; i++) {
        int m = m0 + r0 + i;
        if (m < M) {
            float4 o;
            o.x = fmaxf(acc[i][0] + bb.x, 0.f);
            o.y = fmaxf(acc[i][1] + bb.y, 0.f);
            o.z = fmaxf(acc[i][2] + bb.z, 0.f);
            o.w = fmaxf(acc[i][3] + bb.w, 0.f);
            ((float4*)g_x)[(long long)m * 32 + tx] = o;
        }
    }
}

// ---------------- GEMM2: h2 = x @ W2   [M,128]x[128,64] ----------------
__global__ __launch_bounds__(256) void gemm2_kernel(const float* __restrict__ W2, int M) {
    __shared__ float  Ws[F2 * F3];        // 32 KB
    __shared__ float4 As4[64 * 8];        // 8 KB
    int tid = threadIdx.x;
    int m0  = blockIdx.x * 64;

    const float4* W24 = (const float4*)W2;
    float4* Ws4 = (float4*)Ws;
#pragma unroll
    for (int i = 0; i < 8; i++) Ws4[tid + 256 * i] = W24[tid + 256 * i];

    int tx = tid & 15, ty = tid >> 4;
    float acc[4][4];
#pragma unroll
    for (int i = 0; i < 4; i++)
#pragma unroll
        for (int jj = 0; jj < 4; jj++) acc[i][jj] = 0.f;

    const float* As = (const float*)As4;
    const float4* x4 = (const float4*)g_x;

    for (int kc = 0; kc < 4; kc++) {
        __syncthreads();
#pragma unroll
        for (int i = 0; i < 2; i++) {
            int t   = tid + 256 * i;
            int row = m0 + (t >> 3);
            int c4  = t & 7;
            As4[t] = (row < M) ? x4[(long long)row * 32 + kc * 8 + c4]
                               : make_float4(0.f, 0.f, 0.f, 0.f);
        }
        __syncthreads();
#pragma unroll
        for (int kk = 0; kk < 32; kk++) {
            int k = kc * 32 + kk;
            float4 wv = *(const float4*)&Ws[k * F3 + tx * 4];
#pragma unroll
            for (int i = 0; i < 4; i++) {
                float a = As[(ty * 4 + i) * 32 + kk];
                acc[i][0] += a * wv.x;
                acc[i][1] += a * wv.y;
                acc[i][2] += a * wv.z;
                acc[i][3] += a * wv.w;
            }
        }
    }

#pragma unroll
    for (int i = 0; i < 4; i++) {
        int m = m0 + ty * 4 + i;
        if (m < M) {
            ((float4*)g_h2)[(long long)m * 16 + tx] =
                make_float4(acc[i][0], acc[i][1], acc[i][2], acc[i][3]);
        }
    }
}

// ---------------- scale2: h2h = half(h2*dinv), seed out = h2*dinv (fp32) ----------------
__global__ __launch_bounds__(256) void scale2_kernel(float* __restrict__ out, int M) {
    int i = blockIdx.x * 256 + threadIdx.x;     // over M*16 float4
    if (i >= M * 16) return;
    float r = rinv_of(i >> 4);
    float4 v = ((const float4*)g_h2)[i];
    v.x *= r; v.y *= r; v.z *= r; v.w *= r;
    ((float4*)out)[i] = v;                      // self-loop seed (fp32)
    __half2* hp = (__half2*)g_h2h;
    hp[i * 2 + 0] = __floats2half2_rn(v.x, v.y);
    hp[i * 2 + 1] = __floats2half2_rn(v.z, v.w);
}

// ---------------- epilogue: out = relu(out*dinv + b2)  in place ----------------
__global__ __launch_bounds__(256) void epilogue_kernel(const float* __restrict__ b2,
                                                       float* __restrict__ out, int M) {
    int i = blockIdx.x * 256 + threadIdx.x;
    if (i >= M * 16) return;
    float r = rinv_of(i >> 4);
    float4 a = ((const float4*)out)[i];
    float4 b = *(const float4*)(b2 + (i & 15) * 4);
    float4 o;
    o.x = fmaxf(a.x * r + b.x, 0.f);
    o.y = fmaxf(a.y * r + b.y, 0.f);
    o.z = fmaxf(a.z * r + b.z, 0.f);
    o.w = fmaxf(a.w * r + b.w, 0.f);
    ((float4*)out)[i] = o;
}

// ---------------- launch ----------------
extern "C" void kernel_launch(void* const* d_in, const int* in_sizes, int n_in,
                              void* d_out, int out_size) {
    const float* z  = (const float*)d_in[0];
    const void*  ei = d_in[1];
    const float* W1 = (const float*)d_in[2];
    const float* b1 = (const float*)d_in[3];
    const float* W2 = (const float*)d_in[4];
    const float* b2 = (const float*)d_in[5];
    float* out = (float*)d_out;

    int nE = in_sizes[1] / 2;
    int M  = in_sizes[0] / F1;

    int nb_nodes = (M + 255) / 256;
    int nb_edge  = (nE + 255) / 256;
    long long aggT = (long long)nE * 8;
    int nb_agg   = (int)((aggT + 255) / 256);
    int nb_vec   = (M * 16 + 255) / 256;
    int nb_gemm  = (M + 63) / 64;

    init_kernel<<<nb_nodes, 256>>>((const long long*)ei, M);
    pack_deg_kernel<<<nb_edge, 256>>>(ei, nE);
    scale1_kernel<<<nb_vec, 256>>>((const float4*)z, M);
    agg1_kernel<<<nb_agg, 256>>>(nE);
    gemm1_kernel<<<nb_gemm, 256>>>(W1, b1, M);
    gemm2_kernel<<<nb_gemm, 256>>>(W2, M);
    scale2_kernel<<<nb_vec, 256>>>(out, M);
    agg2_kernel<<<nb_agg, 256>>>(out, nE);
    epilogue_kernel<<<nb_vec, 256>>>(b2, out, M);
}

// round 5
// speedup vs baseline: 1.1959x; 1.1959x over previous
#include <cuda_runtime.h>
#include <cuda_fp16.h>

#define N_NODES 50000
#define F1 64
#define F2 128
#define F3 64
#define MAX_E 800000

// ---------------- device scratch ----------------
__device__ int     g_cnt [N_NODES];          // in-degree (excl. self-loop)
__device__ int2    g_ed  [MAX_E];            // packed {src, dst}
__device__ __half  g_zsh [N_NODES * F1];     // (z * dinv) as fp16, 128B/node
__device__ float   g_agg1[N_NODES * F1];     // seeded with z*dinv (fp32), += zs[s]
__device__ float   g_x   [N_NODES * F2];     // relu(layer1)
__device__ __half  g_h2h [N_NODES * F3];     // (h2 * dinv) as fp16
__device__ int     g_is64;

__device__ __forceinline__ void red4(float* p, float x, float y, float z, float w) {
    asm volatile("red.global.add.v4.f32 [%0], {%1,%2,%3,%4};"
                 :: "l"(p), "f"(x), "f"(y), "f"(z), "f"(w) : "memory");
}

__device__ __forceinline__ float rinv_of(int m) {
    return rsqrtf((float)(g_cnt[m] + 1));
}

// ---------------- init: zero histogram + dtype detect ----------------
__global__ void init_kernel(const long long* ei, int M) {
    int i = blockIdx.x * 256 + threadIdx.x;
    if (i < M) g_cnt[i] = 0;
    if (blockIdx.x == 0 && threadIdx.x == 0) {
        bool ok = true;
#pragma unroll
        for (int k = 0; k < 8; k++) {
            long long v = ei[k];
            if (v < 0 || v >= N_NODES) ok = false;
        }
        g_is64 = ok ? 1 : 0;   // int32 data read as int64 lands out of range
    }
}

// ---------------- pack edges to int2 + degree histogram ----------------
__global__ void pack_deg_kernel(const void* ei, int nE) {
    int e = blockIdx.x * 256 + threadIdx.x;
    if (e >= nE) return;
    int s, d;
    if (g_is64) {
        s = (int)((const long long*)ei)[e];
        d = (int)((const long long*)ei)[(long long)nE + e];
    } else {
        s = ((const int*)ei)[e];
        d = ((const int*)ei)[nE + e];
    }
    g_ed[e] = make_int2(s, d);
    atomicAdd(&g_cnt[d], 1);
}

// ---------------- scale1: zsh = half(z*dinv), seed agg1 = z*dinv (fp32) ----------------
__global__ __launch_bounds__(256) void scale1_kernel(const float4* __restrict__ z4, int M) {
    int i = blockIdx.x * 256 + threadIdx.x;     // over M*16 float4
    if (i >= M * 16) return;
    float r = rinv_of(i >> 4);
    float4 v = z4[i];
    v.x *= r; v.y *= r; v.z *= r; v.w *= r;
    ((float4*)g_agg1)[i] = v;                   // self-loop seed (fp32)
    __half2* hp = (__half2*)g_zsh;
    hp[i * 2 + 0] = __floats2half2_rn(v.x, v.y);
    hp[i * 2 + 1] = __floats2half2_rn(v.z, v.w);
}

// ---- agg: 16 threads/edge, 8B fp16 gather (LDG.64), one red.v4 fp32 each ----
__device__ __forceinline__ void agg_body(const __half* __restrict__ src,
                                         float* __restrict__ dst, int nE) {
    long long t = (long long)blockIdx.x * 256 + threadIdx.x;
    long long e = t >> 4;
    if (e >= nE) return;
    int j = (int)(t & 15);
    int2 ed = g_ed[e];
    float2 raw = ((const float2*)src)[(long long)ed.x * 16 + j];  // 4 halves
    const __half2* h = (const __half2*)&raw;
    float2 f0 = __half22float2(h[0]);
    float2 f1 = __half22float2(h[1]);
    red4(dst + (long long)ed.y * 64 + j * 4, f0.x, f0.y, f1.x, f1.y);
}

__global__ __launch_bounds__(256) void agg1_kernel(int nE) {
    agg_body(g_zsh, g_agg1, nE);
}

__global__ __launch_bounds__(256) void agg2_kernel(float* __restrict__ out, int nE) {
    agg_body(g_h2h, out, nE);
}

// ---------------- GEMM1: x = relu( (agg1*dinv) @ W1 + b1 )  [M,64]x[64,128] ----------------
__global__ __launch_bounds__(256) void gemm1_kernel(const float* __restrict__ W1,
                                                    const float* __restrict__ b1,
                                                    int M) {
    __shared__ float  Ws[F1 * F2];        // 32 KB
    __shared__ float4 As4[64 * 16];       // 16 KB
    int tid = threadIdx.x;
    int m0  = blockIdx.x * 64;

    const float4* W14 = (const float4*)W1;
    float4* Ws4 = (float4*)Ws;
#pragma unroll
    for (int i = 0; i < 8; i++) Ws4[tid + 256 * i] = W14[tid + 256 * i];

    const float4* ag4 = (const float4*)g_agg1;
#pragma unroll
    for (int i = 0; i < 4; i++) {
        int t   = tid + 256 * i;
        int row = m0 + (t >> 4);
        float4 a = make_float4(0.f, 0.f, 0.f, 0.f);
        if (row < M) {
            a = ag4[(long long)row * 16 + (t & 15)];
            float r = rinv_of(row);
            a.x *= r; a.y *= r; a.z *= r; a.w *= r;
        }
        As4[t] = a;
    }
    __syncthreads();

    int tx = tid & 31, ty = tid >> 5;
    int c = tx * 4, r0 = ty * 8;
    float acc[8][4];
#pragma unroll
    for (int i = 0; i < 8; i++)
#pragma unroll
        for (int jj = 0; jj < 4; jj++) acc[i][jj] = 0.f;

    const float* As = (const float*)As4;
#pragma unroll
    for (int k = 0; k < F1; k++) {
        float4 wv = *(const float4*)&Ws[k * F2 + c];
#pragma unroll
        for (int i = 0; i < 8; i++) {
            float a = As[(r0 + i) * F1 + k];
            acc[i][0] += a * wv.x;
            acc[i][1] += a * wv.y;
            acc[i][2] += a * wv.z;
            acc[i][3] += a * wv.w;
        }
    }

    float4 bb = *(const float4*)&b1[c];
#pragma unroll
    for (int i = 0; i < 8; i++) {
        int m = m0 + r0 + i;
        if (m < M) {
            float4 o;
            o.x = fmaxf(acc[i][0] + bb.x, 0.f);
            o.y = fmaxf(acc[i][1] + bb.y, 0.f);
            o.z = fmaxf(acc[i][2] + bb.z, 0.f);
            o.w = fmaxf(acc[i][3] + bb.w, 0.f);
            ((float4*)g_x)[(long long)m * 32 + tx] = o;
        }
    }
}

// -------- GEMM2 (+fused scale2): out_seed = (x@W2)*dinv, h2h = half(same) --------
__global__ __launch_bounds__(256) void gemm2_kernel(const float* __restrict__ W2,
                                                    float* __restrict__ out, int M) {
    __shared__ float  Ws[F2 * F3];        // 32 KB
    __shared__ float4 As4[64 * 8];        // 8 KB
    int tid = threadIdx.x;
    int m0  = blockIdx.x * 64;

    const float4* W24 = (const float4*)W2;
    float4* Ws4 = (float4*)Ws;
#pragma unroll
    for (int i = 0; i < 8; i++) Ws4[tid + 256 * i] = W24[tid + 256 * i];

    int tx = tid & 15, ty = tid >> 4;
    float acc[4][4];
#pragma unroll
    for (int i = 0; i < 4; i++)
#pragma unroll
        for (int jj = 0; jj < 4; jj++) acc[i][jj] = 0.f;

    const float* As = (const float*)As4;
    const float4* x4 = (const float4*)g_x;

    for (int kc = 0; kc < 4; kc++) {
        __syncthreads();
#pragma unroll
        for (int i = 0; i < 2; i++) {
            int t   = tid + 256 * i;
            int row = m0 + (t >> 3);
            int c4  = t & 7;
            As4[t] = (row < M) ? x4[(long long)row * 32 + kc * 8 + c4]
                               : make_float4(0.f, 0.f, 0.f, 0.f);
        }
        __syncthreads();
#pragma unroll
        for (int kk = 0; kk < 32; kk++) {
            int k = kc * 32 + kk;
            float4 wv = *(const float4*)&Ws[k * F3 + tx * 4];
#pragma unroll
            for (int i = 0; i < 4; i++) {
                float a = As[(ty * 4 + i) * 32 + kk];
                acc[i][0] += a * wv.x;
                acc[i][1] += a * wv.y;
                acc[i][2] += a * wv.z;
                acc[i][3] += a * wv.w;
            }
        }
    }

#pragma unroll
    for (int i = 0; i < 4; i++) {
        int m = m0 + ty * 4 + i;
        if (m < M) {
            float r = rinv_of(m);
            float4 v = make_float4(acc[i][0] * r, acc[i][1] * r,
                                   acc[i][2] * r, acc[i][3] * r);
            ((float4*)out)[(long long)m * 16 + tx] = v;        // self-loop seed
            __half2* hp = (__half2*)g_h2h;
            long long b = ((long long)m * 16 + tx) * 2;
            hp[b + 0] = __floats2half2_rn(v.x, v.y);
            hp[b + 1] = __floats2half2_rn(v.z, v.w);
        }
    }
}

// ---------------- epilogue: out = relu(out*dinv + b2)  in place ----------------
__global__ __launch_bounds__(256) void epilogue_kernel(const float* __restrict__ b2,
                                                       float* __restrict__ out, int M) {
    int i = blockIdx.x * 256 + threadIdx.x;
    if (i >= M * 16) return;
    float r = rinv_of(i >> 4);
    float4 a = ((const float4*)out)[i];
    float4 b = *(const float4*)(b2 + (i & 15) * 4);
    float4 o;
    o.x = fmaxf(a.x * r + b.x, 0.f);
    o.y = fmaxf(a.y * r + b.y, 0.f);
    o.z = fmaxf(a.z * r + b.z, 0.f);
    o.w = fmaxf(a.w * r + b.w, 0.f);
    ((float4*)out)[i] = o;
}

// ---------------- launch ----------------
extern "C" void kernel_launch(void* const* d_in, const int* in_sizes, int n_in,
                              void* d_out, int out_size) {
    const float* z  = (const float*)d_in[0];
    const void*  ei = d_in[1];
    const float* W1 = (const float*)d_in[2];
    const float* b1 = (const float*)d_in[3];
    const float* W2 = (const float*)d_in[4];
    const float* b2 = (const float*)d_in[5];
    float* out = (float*)d_out;

    int nE = in_sizes[1] / 2;
    int M  = in_sizes[0] / F1;

    int nb_nodes = (M + 255) / 256;
    int nb_edge  = (nE + 255) / 256;
    long long aggT = (long long)nE * 16;
    int nb_agg   = (int)((aggT + 255) / 256);
    int nb_vec   = (M * 16 + 255) / 256;
    int nb_gemm  = (M + 63) / 64;

    init_kernel<<<nb_nodes, 256>>>((const long long*)ei, M);
    pack_deg_kernel<<<nb_edge, 256>>>(ei, nE);
    scale1_kernel<<<nb_vec, 256>>>((const float4*)z, M);
    agg1_kernel<<<nb_agg, 256>>>(nE);
    gemm1_kernel<<<nb_gemm, 256>>>(W1, b1, M);
    gemm2_kernel<<<nb_gemm, 256>>>(W2, out, M);
    agg2_kernel<<<nb_agg, 256>>>(out, nE);
    epilogue_kernel<<<nb_vec, 256>>>(b2, out, M);
}

// round 6
// speedup vs baseline: 1.5448x; 1.2918x over previous
#include <cuda_runtime.h>
#include <cuda_fp16.h>
#include <cstdint>

#define N_NODES 50000
#define F1 64
#define F2 128
#define F3 64
#define MAX_E 800000

// ---------------- device scratch ----------------
__device__ int     g_cnt  [N_NODES];         // in-degree (excl. self-loop)
__device__ int2    g_ed   [MAX_E];           // packed {src, dst}
__device__ __half  g_zsh  [N_NODES * F1];    // (z * dinv) fp16  (gather source L1)
__device__ __half  g_agg1h[N_NODES * F1];    // fp16 accumulator L1 (seeded with zsh)
__device__ float   g_x    [N_NODES * F2];    // relu(layer1)
__device__ __half  g_h2h  [N_NODES * F3];    // (h2 * dinv) fp16 (gather source L2)
__device__ __half  g_agg2h[N_NODES * F3];    // fp16 accumulator L2 (seeded with h2h)
__device__ int     g_is64;

__device__ __forceinline__ void red4h(__half* p, uint32_t a, uint32_t b,
                                      uint32_t c, uint32_t d) {
    asm volatile("red.global.add.noftz.v4.f16x2 [%0], {%1,%2,%3,%4};"
                 :: "l"(p), "r"(a), "r"(b), "r"(c), "r"(d) : "memory");
}

__device__ __forceinline__ float rinv_of(int m) {
    return rsqrtf((float)(g_cnt[m] + 1));
}

// ---------------- init: zero histogram + dtype detect ----------------
__global__ void init_kernel(const long long* ei, int M) {
    int i = blockIdx.x * 256 + threadIdx.x;
    if (i < M) g_cnt[i] = 0;
    if (blockIdx.x == 0 && threadIdx.x == 0) {
        bool ok = true;
#pragma unroll
        for (int k = 0; k < 8; k++) {
            long long v = ei[k];
            if (v < 0 || v >= N_NODES) ok = false;
        }
        g_is64 = ok ? 1 : 0;   // int32 data read as int64 lands out of range
    }
}

// ---------------- pack edges to int2 + degree histogram ----------------
__global__ void pack_deg_kernel(const void* ei, int nE) {
    int e = blockIdx.x * 256 + threadIdx.x;
    if (e >= nE) return;
    int s, d;
    if (g_is64) {
        s = (int)((const long long*)ei)[e];
        d = (int)((const long long*)ei)[(long long)nE + e];
    } else {
        s = ((const int*)ei)[e];
        d = ((const int*)ei)[nE + e];
    }
    g_ed[e] = make_int2(s, d);
    atomicAdd(&g_cnt[d], 1);
}

// ------- scale1: zsh = half(z*dinv); agg1h seeded with same (self-loop) -------
__global__ __launch_bounds__(256) void scale1_kernel(const float4* __restrict__ z4, int M) {
    int i = blockIdx.x * 256 + threadIdx.x;     // over M*16 float4
    if (i >= M * 16) return;
    float r = rinv_of(i >> 4);
    float4 v = z4[i];
    __half2 h0 = __floats2half2_rn(v.x * r, v.y * r);
    __half2 h1 = __floats2half2_rn(v.z * r, v.w * r);
    ((__half2*)g_zsh)  [i * 2 + 0] = h0;
    ((__half2*)g_zsh)  [i * 2 + 1] = h1;
    ((__half2*)g_agg1h)[i * 2 + 0] = h0;
    ((__half2*)g_agg1h)[i * 2 + 1] = h1;
}

// ---- agg: 8 threads/edge, 16B fp16 gather, one red.v4.f16x2 each ----
__device__ __forceinline__ void agg_body(const __half* __restrict__ src,
                                         __half* __restrict__ dst, int nE) {
    long long t = (long long)blockIdx.x * 256 + threadIdx.x;
    long long e = t >> 3;
    if (e >= nE) return;
    int j = (int)(t & 7);
    int2 ed = g_ed[e];
    uint4 v = ((const uint4*)src)[(long long)ed.x * 8 + j];   // 8 halves
    red4h(dst + (long long)ed.y * 64 + j * 8, v.x, v.y, v.z, v.w);
}

__global__ __launch_bounds__(256) void agg1_kernel(int nE) {
    agg_body(g_zsh, g_agg1h, nE);
}

__global__ __launch_bounds__(256) void agg2_kernel(int nE) {
    agg_body(g_h2h, g_agg2h, nE);
}

// ------- GEMM1: x = relu( (agg1h*dinv) @ W1 + b1 )  [M,64]x[64,128] -------
__global__ __launch_bounds__(256) void gemm1_kernel(const float* __restrict__ W1,
                                                    const float* __restrict__ b1,
                                                    int M) {
    __shared__ float Ws[F1 * F2];         // 32 KB
    __shared__ float As[64 * F1];         // 16 KB
    int tid = threadIdx.x;
    int m0  = blockIdx.x * 64;

    const float4* W14 = (const float4*)W1;
    float4* Ws4 = (float4*)Ws;
#pragma unroll
    for (int i = 0; i < 8; i++) Ws4[tid + 256 * i] = W14[tid + 256 * i];

    // A tile: 64 rows x 64 halves = 512 uint4 loads, convert + scale
    const uint4* ag = (const uint4*)g_agg1h;
#pragma unroll
    for (int i = 0; i < 2; i++) {
        int t   = tid + 256 * i;          // 0..511
        int row = m0 + (t >> 3);
        int c   = t & 7;
        float4 lo = make_float4(0.f,0.f,0.f,0.f), hi = lo;
        if (row < M) {
            uint4 v = ag[(long long)row * 8 + c];
            float r = rinv_of(row);
            float2 a0 = __half22float2(*(const __half2*)&v.x);
            float2 a1 = __half22float2(*(const __half2*)&v.y);
            float2 a2 = __half22float2(*(const __half2*)&v.z);
            float2 a3 = __half22float2(*(const __half2*)&v.w);
            lo = make_float4(a0.x * r, a0.y * r, a1.x * r, a1.y * r);
            hi = make_float4(a2.x * r, a2.y * r, a3.x * r, a3.y * r);
        }
        int base = (t >> 3) * F1 + c * 8;
        *(float4*)&As[base - (m0 ? 0 : 0) - ( (t>>3) - (t>>3) )] = lo; // placeholder avoided below
    }
    // NOTE: rewrite of the A-tile store without the awkward expression above:
    __syncthreads();  // (cheap; ensures no WAR with rewrite below)
#pragma unroll
    for (int i = 0; i < 2; i++) {
        int t   = tid + 256 * i;
        int row = m0 + (t >> 3);
        int c   = t & 7;
        float4 lo = make_float4(0.f,0.f,0.f,0.f), hi = lo;
        if (row < M) {
            uint4 v = ag[(long long)row * 8 + c];
            float r = rinv_of(row);
            float2 a0 = __half22float2(*(const __half2*)&v.x);
            float2 a1 = __half22float2(*(const __half2*)&v.y);
            float2 a2 = __half22float2(*(const __half2*)&v.z);
            float2 a3 = __half22float2(*(const __half2*)&v.w);
            lo = make_float4(a0.x * r, a0.y * r, a1.x * r, a1.y * r);
            hi = make_float4(a2.x * r, a2.y * r, a3.x * r, a3.y * r);
        }
        int base = (t >> 3) * F1 + c * 8;
        *(float4*)&As[base]     = lo;
        *(float4*)&As[base + 4] = hi;
    }
    __syncthreads();

    int tx = tid & 31, ty = tid >> 5;
    int c = tx * 4, r0 = ty * 8;
    float acc[8][4];
#pragma unroll
    for (int i = 0; i < 8; i++)
#pragma unroll
        for (int jj = 0; jj < 4; jj++) acc[i][jj] = 0.f;

#pragma unroll
    for (int k = 0; k < F1; k++) {
        float4 wv = *(const float4*)&Ws[k * F2 + c];
#pragma unroll
        for (int i = 0; i < 8; i++) {
            float a = As[(r0 + i) * F1 + k];
            acc[i][0] += a * wv.x;
            acc[i][1] += a * wv.y;
            acc[i][2] += a * wv.z;
            acc[i][3] += a * wv.w;
        }
    }

    float4 bb = *(const float4*)&b1[c];
#pragma unroll
    for (int i = 0; i < 8; i++) {
        int m = m0 + r0 + i;
        if (m < M) {
            float4 o;
            o.x = fmaxf(acc[i][0] + bb.x, 0.f);
            o.y = fmaxf(acc[i][1] + bb.y, 0.f);
            o.z = fmaxf(acc[i][2] + bb.z, 0.f);
            o.w = fmaxf(acc[i][3] + bb.w, 0.f);
            ((float4*)g_x)[(long long)m * 32 + tx] = o;
        }
    }
}

// ---- GEMM2 (+fused scale2): h2h = agg2h_seed = half((x@W2)*dinv) ----
__global__ __launch_bounds__(256) void gemm2_kernel(const float* __restrict__ W2, int M) {
    __shared__ float  Ws[F2 * F3];        // 32 KB
    __shared__ float4 As4[64 * 8];        // 8 KB
    int tid = threadIdx.x;
    int m0  = blockIdx.x * 64;

    const float4* W24 = (const float4*)W2;
    float4* Ws4 = (float4*)Ws;
#pragma unroll
    for (int i = 0; i < 8; i++) Ws4[tid + 256 * i] = W24[tid + 256 * i];

    int tx = tid & 15, ty = tid >> 4;
    float acc[4][4];
#pragma unroll
    for (int i = 0; i < 4; i++)
#pragma unroll
        for (int jj = 0; jj < 4; jj++) acc[i][jj] = 0.f;

    const float* As = (const float*)As4;
    const float4* x4 = (const float4*)g_x;

    for (int kc = 0; kc < 4; kc++) {
        __syncthreads();
#pragma unroll
        for (int i = 0; i < 2; i++) {
            int t   = tid + 256 * i;
            int row = m0 + (t >> 3);
            int c4  = t & 7;
            As4[t] = (row < M) ? x4[(long long)row * 32 + kc * 8 + c4]
                               : make_float4(0.f, 0.f, 0.f, 0.f);
        }
        __syncthreads();
#pragma unroll
        for (int kk = 0; kk < 32; kk++) {
            int k = kc * 32 + kk;
            float4 wv = *(const float4*)&Ws[k * F3 + tx * 4];
#pragma unroll
            for (int i = 0; i < 4; i++) {
                float a = As[(ty * 4 + i) * 32 + kk];
                acc[i][0] += a * wv.x;
                acc[i][1] += a * wv.y;
                acc[i][2] += a * wv.z;
                acc[i][3] += a * wv.w;
            }
        }
    }

#pragma unroll
    for (int i = 0; i < 4; i++) {
        int m = m0 + ty * 4 + i;
        if (m < M) {
            float r = rinv_of(m);
            __half2 h0 = __floats2half2_rn(acc[i][0] * r, acc[i][1] * r);
            __half2 h1 = __floats2half2_rn(acc[i][2] * r, acc[i][3] * r);
            long long b = (long long)m * 32 + tx * 2;
            ((__half2*)g_h2h)  [b]     = h0;
            ((__half2*)g_h2h)  [b + 1] = h1;
            ((__half2*)g_agg2h)[b]     = h0;    // self-loop seed
            ((__half2*)g_agg2h)[b + 1] = h1;
        }
    }
}

// ---------------- epilogue: out = relu(float(agg2h)*dinv + b2) ----------------
__global__ __launch_bounds__(256) void epilogue_kernel(const float* __restrict__ b2,
                                                       float* __restrict__ out, int M) {
    int i = blockIdx.x * 256 + threadIdx.x;     // over M*8 uint4-of-halves
    if (i >= M * 8) return;
    int m = i >> 3, c = i & 7;
    float r = rinv_of(m);
    uint4 v = ((const uint4*)g_agg2h)[i];
    float2 a0 = __half22float2(*(const __half2*)&v.x);
    float2 a1 = __half22float2(*(const __half2*)&v.y);
    float2 a2 = __half22float2(*(const __half2*)&v.z);
    float2 a3 = __half22float2(*(const __half2*)&v.w);
    float4 blo = *(const float4*)(b2 + c * 8);
    float4 bhi = *(const float4*)(b2 + c * 8 + 4);
    float4 o0, o1;
    o0.x = fmaxf(a0.x * r + blo.x, 0.f);
    o0.y = fmaxf(a0.y * r + blo.y, 0.f);
    o0.z = fmaxf(a1.x * r + blo.z, 0.f);
    o0.w = fmaxf(a1.y * r + blo.w, 0.f);
    o1.x = fmaxf(a2.x * r + bhi.x, 0.f);
    o1.y = fmaxf(a2.y * r + bhi.y, 0.f);
    o1.z = fmaxf(a3.x * r + bhi.z, 0.f);
    o1.w = fmaxf(a3.y * r + bhi.w, 0.f);
    ((float4*)out)[i * 2 + 0] = o0;
    ((float4*)out)[i * 2 + 1] = o1;
}

// ---------------- launch ----------------
extern "C" void kernel_launch(void* const* d_in, const int* in_sizes, int n_in,
                              void* d_out, int out_size) {
    const float* z  = (const float*)d_in[0];
    const void*  ei = d_in[1];
    const float* W1 = (const float*)d_in[2];
    const float* b1 = (const float*)d_in[3];
    const float* W2 = (const float*)d_in[4];
    const float* b2 = (const float*)d_in[5];
    float* out = (float*)d_out;

    int nE = in_sizes[1] / 2;
    int M  = in_sizes[0] / F1;

    int nb_nodes = (M + 255) / 256;
    int nb_edge  = (nE + 255) / 256;
    long long aggT = (long long)nE * 8;
    int nb_agg   = (int)((aggT + 255) / 256);
    int nb_vec   = (M * 16 + 255) / 256;
    int nb_epi   = (M * 8 + 255) / 256;
    int nb_gemm  = (M + 63) / 64;

    init_kernel<<<nb_nodes, 256>>>((const long long*)ei, M);
    pack_deg_kernel<<<nb_edge, 256>>>(ei, nE);
    scale1_kernel<<<nb_vec, 256>>>((const float4*)z, M);
    agg1_kernel<<<nb_agg, 256>>>(nE);
    gemm1_kernel<<<nb_gemm, 256>>>(W1, b1, M);
    gemm2_kernel<<<nb_gemm, 256>>>(W2, M);
    agg2_kernel<<<nb_agg, 256>>>(nE);
    epilogue_kernel<<<nb_epi, 256>>>(b2, out, M);
}